// round 2
// baseline (speedup 1.0000x reference)
#include <cuda_runtime.h>
#include <math_constants.h>

// Problem constants
#define B_   4096
#define L_   200
#define D_   256
#define THREADS 256
#define NWARP 8

__device__ __forceinline__ float dot4(float4 a, float4 b) {
    return a.x*b.x + a.y*b.y + a.z*b.z + a.w*b.w;
}

__device__ __forceinline__ float warp_red_sum(float v) {
#pragma unroll
    for (int o = 16; o > 0; o >>= 1) v += __shfl_xor_sync(0xffffffffu, v, o);
    return v;
}

__device__ __forceinline__ float warp_red_max(float v) {
#pragma unroll
    for (int o = 16; o > 0; o >>= 1) v = fmaxf(v, __shfl_xor_sync(0xffffffffu, v, o));
    return v;
}

__global__ void __launch_bounds__(THREADS)
sic_kernel(const int*   __restrict__ items,
           const int*   __restrict__ dts,
           const int*   __restrict__ mask,      // bool serialized as int32
           const int*   __restrict__ pos,
           const int*   __restrict__ neg,
           const float* __restrict__ emb,
           const float* __restrict__ gate_tab,
           const float* __restrict__ raw_tau,
           float*       __restrict__ pos_score,
           float*       __restrict__ neg_score,
           float*       __restrict__ attn_out)
{
    const int b    = blockIdx.x;
    const int tid  = threadIdx.x;
    const int lane = tid & 31;
    const int warp = tid >> 5;

    __shared__ float s_lp[L_];   // logits (pos)
    __shared__ float s_sp[L_];   // raw sim (pos)
    __shared__ float s_ln[L_];   // logits (neg)
    __shared__ float s_sn[L_];   // raw sim (neg)
    __shared__ float red[2 * NWARP];

    // tau = softplus(raw_tau) + 1e-6  (numerically stable softplus)
    float inv_tau;
    {
        float rt = __ldg(raw_tau);
        float sp = (rt > 20.0f) ? rt : log1pf(__expf(rt));
        inv_tau = 1.0f / (sp + 1e-6f);
    }

    // Register-resident q chunks: lane owns dims [lane*8, lane*8+8)
    const float4* qprow = (const float4*)(emb + (size_t)__ldg(pos + b) * D_);
    const float4* qnrow = (const float4*)(emb + (size_t)__ldg(neg + b) * D_);
    const float4 qp0 = __ldg(qprow + lane * 2);
    const float4 qp1 = __ldg(qprow + lane * 2 + 1);
    const float4 qn0 = __ldg(qnrow + lane * 2);
    const float4 qn1 = __ldg(qnrow + lane * 2 + 1);

    // Gather + dual dot-product pass. Warp-strided over L.
    for (int l = warp; l < L_; l += NWARP) {
        const int item = __ldg(items + b * L_ + l);
        const float4* kr = (const float4*)(emb + (size_t)item * D_);
        const float4 k0 = __ldg(kr + lane * 2);
        const float4 k1 = __ldg(kr + lane * 2 + 1);
        float dp = dot4(k0, qp0) + dot4(k1, qp1);
        float dn = dot4(k0, qn0) + dot4(k1, qn1);
        dp = warp_red_sum(dp);
        dn = warp_red_sum(dn);
        if (lane == 0) {
            const float g  = __ldg(gate_tab + __ldg(dts + b * L_ + l));
            const bool  m  = __ldg(mask + b * L_ + l) != 0;
            const float sc = g * inv_tau;
            s_sp[l] = dp;
            s_sn[l] = dn;
            s_lp[l] = m ? dp * sc : -CUDART_INF_F;
            s_ln[l] = m ? dn * sc : -CUDART_INF_F;
        }
    }
    __syncthreads();

    // ---- POS: softmax + score = sum(e*sim)/sum(e); emit attn ----
    {
        const float lg  = (tid < L_) ? s_lp[tid] : -CUDART_INF_F;
        float wm = warp_red_max(lg);
        if (lane == 0) red[warp] = wm;
        __syncthreads();
        float mx = red[0];
#pragma unroll
        for (int i = 1; i < NWARP; i++) mx = fmaxf(mx, red[i]);
        __syncthreads();   // before reusing red

        const float e = (tid < L_) ? __expf(lg - mx) : 0.0f;
        const float t = (tid < L_) ? e * s_sp[tid]   : 0.0f;
        float se = warp_red_sum(e);
        float st = warp_red_sum(t);
        if (lane == 0) { red[warp] = se; red[NWARP + warp] = st; }
        __syncthreads();
        float Se = 0.0f, St = 0.0f;
#pragma unroll
        for (int i = 0; i < NWARP; i++) { Se += red[i]; St += red[NWARP + i]; }

        if (tid < L_) attn_out[(size_t)b * L_ + tid] = e / Se;
        if (tid == 0) pos_score[b] = St / Se;
        __syncthreads();   // before reusing red for neg
    }

    // ---- NEG: softmax + score (no attn output) ----
    {
        const float lg  = (tid < L_) ? s_ln[tid] : -CUDART_INF_F;
        float wm = warp_red_max(lg);
        if (lane == 0) red[warp] = wm;
        __syncthreads();
        float mx = red[0];
#pragma unroll
        for (int i = 1; i < NWARP; i++) mx = fmaxf(mx, red[i]);
        __syncthreads();

        const float e = (tid < L_) ? __expf(lg - mx) : 0.0f;
        const float t = (tid < L_) ? e * s_sn[tid]   : 0.0f;
        float se = warp_red_sum(e);
        float st = warp_red_sum(t);
        if (lane == 0) { red[warp] = se; red[NWARP + warp] = st; }
        __syncthreads();
        float Se = 0.0f, St = 0.0f;
#pragma unroll
        for (int i = 0; i < NWARP; i++) { Se += red[i]; St += red[NWARP + i]; }

        if (tid == 0) neg_score[b] = St / Se;
    }
}

extern "C" void kernel_launch(void* const* d_in, const int* in_sizes, int n_in,
                              void* d_out, int out_size)
{
    // Input order per reference setup_inputs():
    // 0: items_pad [B,L] int32
    // 1: dts_pad   [B,L] int32
    // 2: mask      [B,L] bool -> serialized int32
    // 3: pos_items [B]   int32
    // 4: neg_items [B]   int32
    // 5: item_emb  [NUM_ITEMS, D] float32
    // 6: dt_gate   [NUM_DT, 1]    float32
    // 7: raw_tau   scalar         float32
    const int*   items    = (const int*)d_in[0];
    const int*   dts      = (const int*)d_in[1];
    const int*   mask     = (const int*)d_in[2];
    const int*   pos      = (const int*)d_in[3];
    const int*   neg      = (const int*)d_in[4];
    const float* emb      = (const float*)d_in[5];
    const float* gate_tab = (const float*)d_in[6];
    const float* raw_tau  = (const float*)d_in[7];

    // Output: pos_score [B], neg_score [B], attn_pos [B,L] concatenated
    float* out       = (float*)d_out;
    float* pos_score = out;
    float* neg_score = out + B_;
    float* attn_out  = out + 2 * B_;

    sic_kernel<<<B_, THREADS>>>(items, dts, mask, pos, neg, emb, gate_tab,
                                raw_tau, pos_score, neg_score, attn_out);
}

// round 15
// speedup vs baseline: 1.2997x; 1.2997x over previous
#include <cuda_runtime.h>
#include <math_constants.h>
#include <cstdint>

#define B_   4096
#define L_   200
#define D_   256
#define THREADS 256
#define NWARP 8
#define DEPTH 4                      // per-warp cp.async pipeline depth
#define ROWS_PER_WARP (L_ / NWARP)   // 25
#define MAIN_ROWS (ROWS_PER_WARP - DEPTH)   // 21

__device__ __forceinline__ float dot4(float4 a, float4 b) {
    return a.x*b.x + a.y*b.y + a.z*b.z + a.w*b.w;
}

__device__ __forceinline__ float warp_red_sum(float v) {
#pragma unroll
    for (int o = 16; o > 0; o >>= 1) v += __shfl_xor_sync(0xffffffffu, v, o);
    return v;
}

__device__ __forceinline__ float warp_red_max(float v) {
#pragma unroll
    for (int o = 16; o > 0; o >>= 1) v = fmaxf(v, __shfl_xor_sync(0xffffffffu, v, o));
    return v;
}

__device__ __forceinline__ void cp_async16(uint32_t dst, const void* src) {
    asm volatile("cp.async.cg.shared.global [%0], [%1], 16;\n" :: "r"(dst), "l"(src));
}
__device__ __forceinline__ void cp_commit() {
    asm volatile("cp.async.commit_group;\n");
}
template <int N>
__device__ __forceinline__ void cp_wait() {
    asm volatile("cp.async.wait_group %0;\n" :: "n"(N));
}

__global__ void __launch_bounds__(THREADS, 6)
sic_kernel(const int*   __restrict__ items,
           const int*   __restrict__ dts,
           const int*   __restrict__ mask,      // bool serialized as int32
           const int*   __restrict__ pos,
           const int*   __restrict__ neg,
           const float* __restrict__ emb,
           const float* __restrict__ gate_tab,
           const float* __restrict__ raw_tau,
           float*       __restrict__ pos_score,
           float*       __restrict__ neg_score,
           float*       __restrict__ attn_out)
{
    const int b    = blockIdx.x;
    const int tid  = threadIdx.x;
    const int lane = tid & 31;
    const int warp = tid >> 5;

    __shared__ float buf[NWARP][DEPTH][D_];   // 32 KB: per-warp staging rings
    __shared__ int   s_item[L_];
    __shared__ float s_scale[L_];             // gate * inv_tau
    __shared__ float s_minf[L_];              // 0 if valid, -inf if masked
    __shared__ float s_sp[L_];                // raw sim (pos)
    __shared__ float s_sn[L_];                // raw sim (neg)
    __shared__ float red[2 * NWARP];

    // tau = softplus(raw_tau) + 1e-6
    float inv_tau;
    {
        float rt = __ldg(raw_tau);
        float sp = (rt > 20.0f) ? rt : log1pf(__expf(rt));
        inv_tau = 1.0f / (sp + 1e-6f);
    }

    // Phase 0: broadcast per-row scalars through smem (parallel, no serial deps)
    if (tid < L_) {
        s_item[tid]  = __ldg(items + b * L_ + tid);
        const float g = __ldg(gate_tab + __ldg(dts + b * L_ + tid));
        const bool  m = __ldg(mask + b * L_ + tid) != 0;
        s_scale[tid] = g * inv_tau;
        s_minf[tid]  = m ? 0.0f : -CUDART_INF_F;
    }

    // Register-resident q chunks: lane owns dims [lane*8, lane*8+8)
    const float4* qprow = (const float4*)(emb + (size_t)__ldg(pos + b) * D_);
    const float4* qnrow = (const float4*)(emb + (size_t)__ldg(neg + b) * D_);
    const float4 qp0 = __ldg(qprow + lane * 2);
    const float4 qp1 = __ldg(qprow + lane * 2 + 1);
    const float4 qn0 = __ldg(qnrow + lane * 2);
    const float4 qn1 = __ldg(qnrow + lane * 2 + 1);

    __syncthreads();

    // Per-warp smem base (generic -> shared address space)
    const uint32_t buf_base =
        (uint32_t)__cvta_generic_to_shared(&buf[warp][0][0]);

    // Stage row j (this warp's j-th row; global row l = warp + 8*j)
    auto stage = [&](int j) {
        const int l    = warp + NWARP * j;
        const int item = s_item[l];
        const char* src = (const char*)(emb + (size_t)item * D_) + lane * 16;
        const uint32_t dst = buf_base + (uint32_t)(j & (DEPTH - 1)) * (D_ * 4)
                           + lane * 16;
        cp_async16(dst,       src);
        cp_async16(dst + 512, src + 512);
        cp_commit();
    };

    auto consume = [&](int j) {
        const float* rowbuf = &buf[warp][j & (DEPTH - 1)][0];
        const float4 k0 = *(const float4*)(rowbuf + lane * 8);
        const float4 k1 = *(const float4*)(rowbuf + lane * 8 + 4);
        float dp = dot4(k0, qp0) + dot4(k1, qp1);
        float dn = dot4(k0, qn0) + dot4(k1, qn1);
        dp = warp_red_sum(dp);
        dn = warp_red_sum(dn);
        if (lane == 0) {
            const int l = warp + NWARP * j;
            s_sp[l] = dp;
            s_sn[l] = dn;
        }
    };

    // Prologue: fill the pipeline (DEPTH groups in flight per thread)
#pragma unroll
    for (int j = 0; j < DEPTH; ++j) stage(j);

    // Main loop: steady state, always DEPTH groups in flight, so
    // wait_group<DEPTH-1> provably drains row j's group.
    for (int j = 0; j < MAIN_ROWS; ++j) {
        cp_wait<DEPTH - 1>();       // this thread's row-j group complete
        __syncwarp();               // all lanes' row-j copies visible

        const float* rowbuf = &buf[warp][j & (DEPTH - 1)][0];
        const float4 k0 = *(const float4*)(rowbuf + lane * 8);
        const float4 k1 = *(const float4*)(rowbuf + lane * 8 + 4);
        float dp = dot4(k0, qp0) + dot4(k1, qp1);   // consumes slot data
        float dn = dot4(k0, qn0) + dot4(k1, qn1);

        __syncwarp();               // all lanes consumed slot j&3
        stage(j + DEPTH);           // refill (overlaps reduction below)

        dp = warp_red_sum(dp);
        dn = warp_red_sum(dn);
        if (lane == 0) {
            const int l = warp + NWARP * j;
            s_sp[l] = dp;
            s_sn[l] = dn;
        }
    }

    // Drain: fewer than DEPTH groups pending in the tail, so wait_group<DEPTH-1>
    // would NOT block (the R12 bug). Wait for everything, then consume.
    cp_wait<0>();
    __syncwarp();
#pragma unroll
    for (int j = MAIN_ROWS; j < ROWS_PER_WARP; ++j) consume(j);

    __syncthreads();

    // ---- POS: softmax + score = sum(e*sim)/sum(e); emit attn ----
    {
        const float lg = (tid < L_)
            ? s_sp[tid] * s_scale[tid] + s_minf[tid] : -CUDART_INF_F;
        float wm = warp_red_max(lg);
        if (lane == 0) red[warp] = wm;
        __syncthreads();
        float mx = red[0];
#pragma unroll
        for (int i = 1; i < NWARP; i++) mx = fmaxf(mx, red[i]);
        __syncthreads();

        const float e = (tid < L_) ? __expf(lg - mx) : 0.0f;
        const float t = (tid < L_) ? e * s_sp[tid]   : 0.0f;
        float se = warp_red_sum(e);
        float st = warp_red_sum(t);
        if (lane == 0) { red[warp] = se; red[NWARP + warp] = st; }
        __syncthreads();
        float Se = 0.0f, St = 0.0f;
#pragma unroll
        for (int i = 0; i < NWARP; i++) { Se += red[i]; St += red[NWARP + i]; }

        if (tid < L_) attn_out[(size_t)b * L_ + tid] = e / Se;
        if (tid == 0) pos_score[b] = St / Se;
        __syncthreads();
    }

    // ---- NEG: softmax + score ----
    {
        const float lg = (tid < L_)
            ? s_sn[tid] * s_scale[tid] + s_minf[tid] : -CUDART_INF_F;
        float wm = warp_red_max(lg);
        if (lane == 0) red[warp] = wm;
        __syncthreads();
        float mx = red[0];
#pragma unroll
        for (int i = 1; i < NWARP; i++) mx = fmaxf(mx, red[i]);
        __syncthreads();

        const float e = (tid < L_) ? __expf(lg - mx) : 0.0f;
        const float t = (tid < L_) ? e * s_sn[tid]   : 0.0f;
        float se = warp_red_sum(e);
        float st = warp_red_sum(t);
        if (lane == 0) { red[warp] = se; red[NWARP + warp] = st; }
        __syncthreads();
        float Se = 0.0f, St = 0.0f;
#pragma unroll
        for (int i = 0; i < NWARP; i++) { Se += red[i]; St += red[NWARP + i]; }

        if (tid == 0) neg_score[b] = St / Se;
    }
}

extern "C" void kernel_launch(void* const* d_in, const int* in_sizes, int n_in,
                              void* d_out, int out_size)
{
    const int*   items    = (const int*)d_in[0];
    const int*   dts      = (const int*)d_in[1];
    const int*   mask     = (const int*)d_in[2];
    const int*   pos      = (const int*)d_in[3];
    const int*   neg      = (const int*)d_in[4];
    const float* emb      = (const float*)d_in[5];
    const float* gate_tab = (const float*)d_in[6];
    const float* raw_tau  = (const float*)d_in[7];

    float* out       = (float*)d_out;
    float* pos_score = out;
    float* neg_score = out + B_;
    float* attn_out  = out + 2 * B_;

    sic_kernel<<<B_, THREADS>>>(items, dts, mask, pos, neg, emb, gate_tab,
                                raw_tau, pos_score, neg_score, attn_out);
}